// round 1
// baseline (speedup 1.0000x reference)
#include <cuda_runtime.h>
#include <float.h>
#include <math.h>

#define NWIN 30000
#define NEX  30000
#define EDG  480000
#define HDIM 512
#define NLAYERS 4
#define KWIN 1949
#define KEXP 100
#define NOUT 100

// ---------------- scratch (static device globals; no allocation) ----------------
__device__ float g_hw0[NWIN*HDIM];
__device__ float g_hw1[NWIN*HDIM];
__device__ float g_he0[NEX*HDIM];
__device__ float g_he1[NEX*HDIM];
__device__ float g_a0[NWIN*HDIM];   // agg sum (near), later reused as pooled
__device__ float g_a1[NWIN*HDIM];   // agg sum (refer)
__device__ float g_a2[NEX*HDIM];    // agg sum (close)
__device__ float g_tmp[NWIN*HDIM];  // GEMM-chain accumulator / projection temp
__device__ float g_wsum[HDIM*HDIM]; // Wr_near[l] + Wr_refer[l]
__device__ float g_rn[NWIN];
__device__ float g_rr[NWIN];
__device__ float g_rc[NEX];
__device__ float g_score[NEX];
__device__ unsigned g_mxu[NWIN];
__device__ float g_z[NWIN];
__device__ float g_ex[EDG];

// ---------------- SGEMM: D = act(postscale*(rowscale[m]*A@B + bias[n] + beta*Cin)) ----
// A[M,K] row-major, B[K,N] row-major, Cin/D [M,N] row-major.
__launch_bounds__(256)
__global__ void sgemm(int M, int N, int K,
                      const float* __restrict__ A,
                      const float* __restrict__ B,
                      const float* __restrict__ Cin,
                      float* __restrict__ D,
                      const float* __restrict__ bias,
                      const float* __restrict__ rowscale,
                      float beta, float postscale, int act)
{
    __shared__ float As[8][128];
    __shared__ float Bs[8][128];
    const int tid = threadIdx.x;
    const int bm = blockIdx.y * 128;
    const int bn = blockIdx.x * 128;
    const int aRow = tid >> 1;            // 0..127
    const int aCol = (tid & 1) * 4;       // 0 or 4
    const int bRow = tid >> 5;            // 0..7
    const int bCol = (tid & 31) * 4;      // 0..124
    const int tx = tid & 15, ty = tid >> 4;

    float acc[8][8];
#pragma unroll
    for (int i = 0; i < 8; i++)
#pragma unroll
        for (int j = 0; j < 8; j++) acc[i][j] = 0.f;

    const bool aRowOk = (bm + aRow) < M;
    const float* Aptr = A + (size_t)(bm + aRow) * K;

    for (int kt = 0; kt < K; kt += 8) {
        // load A tile (scalar; K may be ragged/unaligned e.g. 1949)
#pragma unroll
        for (int i = 0; i < 4; i++) {
            int k = kt + aCol + i;
            As[aCol + i][aRow] = (aRowOk && k < K) ? Aptr[k] : 0.f;
        }
        // load B tile (vectorized when fully in-bounds)
        {
            int k = kt + bRow;
            bool kok = k < K;
            const float* Bp = B + (size_t)k * N + bn + bCol;
            if (kok && (bn + bCol + 3) < N) {
                float4 v = *(const float4*)Bp;
                Bs[bRow][bCol + 0] = v.x;
                Bs[bRow][bCol + 1] = v.y;
                Bs[bRow][bCol + 2] = v.z;
                Bs[bRow][bCol + 3] = v.w;
            } else {
#pragma unroll
                for (int i = 0; i < 4; i++)
                    Bs[bRow][bCol + i] = (kok && (bn + bCol + i) < N) ? Bp[i] : 0.f;
            }
        }
        __syncthreads();
#pragma unroll
        for (int k = 0; k < 8; k++) {
            float a[8], b[8];
#pragma unroll
            for (int i = 0; i < 8; i++) a[i] = As[k][ty * 8 + i];
#pragma unroll
            for (int j = 0; j < 8; j++) b[j] = Bs[k][tx * 8 + j];
#pragma unroll
            for (int i = 0; i < 8; i++)
#pragma unroll
                for (int j = 0; j < 8; j++) acc[i][j] += a[i] * b[j];
        }
        __syncthreads();
    }

#pragma unroll
    for (int i = 0; i < 8; i++) {
        int m = bm + ty * 8 + i;
        if (m >= M) continue;
        float rs = rowscale ? rowscale[m] : 1.f;
#pragma unroll
        for (int j = 0; j < 8; j++) {
            int n = bn + tx * 8 + j;
            if (n >= N) continue;
            float v = acc[i][j] * rs;
            if (bias) v += bias[n];
            if (beta != 0.f) v += beta * Cin[(size_t)m * N + n];
            v *= postscale;
            if (act) v = v > 0.f ? v : 0.2f * v;
            D[(size_t)m * N + n] = v;
        }
    }
}

// ---------------- elementwise / scatter kernels ----------------
__global__ void zero_kernel(float* __restrict__ p, long long n4)
{
    long long i = (long long)blockIdx.x * blockDim.x + threadIdx.x;
    if (i < n4) ((float4*)p)[i] = make_float4(0.f, 0.f, 0.f, 0.f);
}

__global__ void count_deg(const int* __restrict__ ed, float* __restrict__ cnt, int n)
{
    int e = blockIdx.x * blockDim.x + threadIdx.x;
    if (e < n) atomicAdd(&cnt[ed[e]], 1.f);
}

__global__ void recip_kernel(float* __restrict__ c, int n)
{
    int i = blockIdx.x * blockDim.x + threadIdx.x;
    if (i < n) c[i] = 1.f / fmaxf(c[i], 1.f);
}

__global__ void wsum_add(const float* __restrict__ a, const float* __restrict__ b,
                         float* __restrict__ o, int n)
{
    int i = blockIdx.x * blockDim.x + threadIdx.x;
    if (i < n) o[i] = a[i] + b[i];
}

// out[dst] += src_row[src] (sum aggregation; mean's divide folded into GEMM rowscale)
__global__ void scatter_add(const float* __restrict__ src,
                            const int* __restrict__ es,
                            const int* __restrict__ ed,
                            float* __restrict__ out)
{
    long long idx = (long long)blockIdx.x * blockDim.x + threadIdx.x;
    const long long tot = (long long)EDG * (HDIM / 4);
    if (idx >= tot) return;
    int e = (int)(idx >> 7);      // HDIM/4 == 128
    int c = (int)(idx & 127);
    int s = es[e], d = ed[e];
    float4 v = ((const float4*)(src + (size_t)s * HDIM))[c];
    float* o = out + (size_t)d * HDIM + c * 4;
    atomicAdd(o + 0, v.x);
    atomicAdd(o + 1, v.y);
    atomicAdd(o + 2, v.z);
    atomicAdd(o + 3, v.w);
}

__global__ void gemv_score(const float* __restrict__ he, const float* __restrict__ w,
                           float* __restrict__ sc)
{
    int row = blockIdx.x * 8 + (threadIdx.x >> 5);
    if (row >= NEX) return;
    int lane = threadIdx.x & 31;
    const float* r = he + (size_t)row * HDIM;
    float s = 0.f;
#pragma unroll
    for (int k = lane; k < HDIM; k += 32) s += r[k] * w[k];
#pragma unroll
    for (int o = 16; o; o >>= 1) s += __shfl_down_sync(0xFFFFFFFFu, s, o);
    if (lane == 0) sc[row] = s;
}

__device__ __forceinline__ unsigned f2ord(float f)
{
    unsigned u = __float_as_uint(f);
    return (u & 0x80000000u) ? ~u : (u | 0x80000000u);
}
__device__ __forceinline__ float ord2f(unsigned u)
{
    return __uint_as_float((u & 0x80000000u) ? (u & 0x7FFFFFFFu) : ~u);
}

__global__ void init_mx(unsigned* __restrict__ mxu, int n)
{
    int i = blockIdx.x * blockDim.x + threadIdx.x;
    if (i < n) mxu[i] = f2ord(-FLT_MAX);
}

__global__ void edge_max(const float* __restrict__ score, const int* __restrict__ es,
                         const int* __restrict__ ed, unsigned* __restrict__ mxu)
{
    int e = blockIdx.x * blockDim.x + threadIdx.x;
    if (e >= EDG) return;
    atomicMax(&mxu[ed[e]], f2ord(score[es[e]]));
}

__global__ void edge_exp(const float* __restrict__ score, const int* __restrict__ es,
                         const int* __restrict__ ed, const unsigned* __restrict__ mxu,
                         float* __restrict__ z, float* __restrict__ ex)
{
    int e = blockIdx.x * blockDim.x + threadIdx.x;
    if (e >= EDG) return;
    float s = score[es[e]];
    float m = ord2f(mxu[ed[e]]);
    float v = expf(s - m);
    ex[e] = v;
    atomicAdd(&z[ed[e]], v);
}

__global__ void edge_norm(const int* __restrict__ ed, const float* __restrict__ z,
                          float* __restrict__ ex)
{
    int e = blockIdx.x * blockDim.x + threadIdx.x;
    if (e >= EDG) return;
    ex[e] = ex[e] / fmaxf(z[ed[e]], 1e-12f);
}

__global__ void pool_scatter(const float* __restrict__ he, const int* __restrict__ es,
                             const int* __restrict__ ed, const float* __restrict__ w,
                             float* __restrict__ out)
{
    long long idx = (long long)blockIdx.x * blockDim.x + threadIdx.x;
    const long long tot = (long long)EDG * (HDIM / 4);
    if (idx >= tot) return;
    int e = (int)(idx >> 7);
    int c = (int)(idx & 127);
    int s = es[e], d = ed[e];
    float we = w[e];
    float4 v = ((const float4*)(he + (size_t)s * HDIM))[c];
    float* o = out + (size_t)d * HDIM + c * 4;
    atomicAdd(o + 0, we * v.x);
    atomicAdd(o + 1, we * v.y);
    atomicAdd(o + 2, we * v.z);
    atomicAdd(o + 3, we * v.w);
}

// t = hw + 0.5*pool
__global__ void addmix(const float* __restrict__ hw, const float* __restrict__ pool,
                       float* __restrict__ o, long long n4)
{
    long long i = (long long)blockIdx.x * blockDim.x + threadIdx.x;
    if (i >= n4) return;
    float4 a = ((const float4*)hw)[i];
    float4 b = ((const float4*)pool)[i];
    ((float4*)o)[i] = make_float4(a.x + 0.5f * b.x, a.y + 0.5f * b.y,
                                  a.z + 0.5f * b.z, a.w + 0.5f * b.w);
}

// ---------------- host orchestration ----------------
static inline void gemm_launch(int M, int N, int K, const float* A, const float* B,
                               const float* Cin, float* D, const float* bias,
                               const float* rs, float beta, float ps, int act)
{
    dim3 grid((N + 127) / 128, (M + 127) / 128);
    sgemm<<<grid, 256>>>(M, N, K, A, B, Cin, D, bias, rs, beta, ps, act);
}

static inline void zero_buf(float* p, long long nfloats)
{
    long long n4 = nfloats / 4;
    zero_kernel<<<(unsigned)((n4 + 255) / 256), 256>>>(p, n4);
}

extern "C" void kernel_launch(void* const* d_in, const int* in_sizes, int n_in,
                              void* d_out, int out_size)
{
    const float* x_window  = (const float*)d_in[0];
    const float* x_example = (const float*)d_in[1];
    const int*   e_near    = (const int*)d_in[2];
    const int*   e_close   = (const int*)d_in[3];
    const int*   e_refer   = (const int*)d_in[4];
    const float* W_win     = (const float*)d_in[5];
    const float* W_exp     = (const float*)d_in[6];
    const float* W_post    = (const float*)d_in[7];
    // d_in[8] = W_ey (computed-but-unused in reference; skipped)
    const float* Wl_near   = (const float*)d_in[9];
    const float* Wr_near   = (const float*)d_in[10];
    const float* b_near    = (const float*)d_in[11];
    const float* Wl_close  = (const float*)d_in[12];
    const float* Wr_close  = (const float*)d_in[13];
    const float* b_close   = (const float*)d_in[14];
    const float* Wl_refer  = (const float*)d_in[15];
    const float* Wr_refer  = (const float*)d_in[16];
    const float* b_refer   = (const float*)d_in[17];
    const float* w_pool    = (const float*)d_in[18];
    const float* W_lin     = (const float*)d_in[19];
    const float* b_lin     = (const float*)d_in[20];
    float* out = (float*)d_out;

    float *hw[2], *he[2], *a0, *a1, *a2, *tmp, *wsum, *rn, *rr, *rc, *score, *z, *ex;
    unsigned* mxu;
    cudaGetSymbolAddress((void**)&hw[0], g_hw0);
    cudaGetSymbolAddress((void**)&hw[1], g_hw1);
    cudaGetSymbolAddress((void**)&he[0], g_he0);
    cudaGetSymbolAddress((void**)&he[1], g_he1);
    cudaGetSymbolAddress((void**)&a0, g_a0);
    cudaGetSymbolAddress((void**)&a1, g_a1);
    cudaGetSymbolAddress((void**)&a2, g_a2);
    cudaGetSymbolAddress((void**)&tmp, g_tmp);
    cudaGetSymbolAddress((void**)&wsum, g_wsum);
    cudaGetSymbolAddress((void**)&rn, g_rn);
    cudaGetSymbolAddress((void**)&rr, g_rr);
    cudaGetSymbolAddress((void**)&rc, g_rc);
    cudaGetSymbolAddress((void**)&score, g_score);
    cudaGetSymbolAddress((void**)&mxu, g_mxu);
    cudaGetSymbolAddress((void**)&z, g_z);
    cudaGetSymbolAddress((void**)&ex, g_ex);

    const int* near_s = e_near;           const int* near_d = e_near + EDG;
    const int* close_s = e_close;         const int* close_d = e_close + EDG;
    const int* refer_s = e_refer;         const int* refer_d = e_refer + EDG;

    const long long scat_tot = (long long)EDG * (HDIM / 4);
    const unsigned scat_blocks = (unsigned)((scat_tot + 255) / 256);
    const unsigned edge_blocks = (EDG + 255) / 256;

    // --- degree reciprocals (1/max(deg,1)) for segment_mean folded into GEMM ---
    zero_buf(rn, NWIN); zero_buf(rr, NWIN); zero_buf(rc, NEX);
    count_deg<<<edge_blocks, 256>>>(near_d, rn, EDG);
    count_deg<<<edge_blocks, 256>>>(refer_d, rr, EDG);
    count_deg<<<edge_blocks, 256>>>(close_d, rc, EDG);
    recip_kernel<<<(NWIN + 255) / 256, 256>>>(rn, NWIN);
    recip_kernel<<<(NWIN + 255) / 256, 256>>>(rr, NWIN);
    recip_kernel<<<(NEX + 255) / 256, 256>>>(rc, NEX);

    // --- input projections: h = lrelu(lrelu(x@W)@W_post) ---
    gemm_launch(NEX, HDIM, KEXP, x_example, W_exp, nullptr, tmp, nullptr, nullptr, 0.f, 1.f, 1);
    gemm_launch(NEX, HDIM, HDIM, tmp, W_post, nullptr, he[0], nullptr, nullptr, 0.f, 1.f, 1);
    gemm_launch(NWIN, HDIM, KWIN, x_window, W_win, nullptr, tmp, nullptr, nullptr, 0.f, 1.f, 1);
    gemm_launch(NWIN, HDIM, HDIM, tmp, W_post, nullptr, hw[0], nullptr, nullptr, 0.f, 1.f, 1);

    // --- SAGE layers ---
    int cur = 0;
    for (int l = 0; l < NLAYERS; l++) {
        int nxt = cur ^ 1;
        const float* WlN = Wl_near + (size_t)l * HDIM * HDIM;
        const float* WrN = Wr_near + (size_t)l * HDIM * HDIM;
        const float* WlR = Wl_refer + (size_t)l * HDIM * HDIM;
        const float* WrR = Wr_refer + (size_t)l * HDIM * HDIM;
        const float* WlC = Wl_close + (size_t)l * HDIM * HDIM;
        const float* WrC = Wr_close + (size_t)l * HDIM * HDIM;
        const float* bN = b_near + (size_t)l * HDIM;
        const float* bR = b_refer + (size_t)l * HDIM;
        const float* bC = b_close + (size_t)l * HDIM;

        zero_buf(a0, (long long)NWIN * HDIM);
        zero_buf(a1, (long long)NWIN * HDIM);
        zero_buf(a2, (long long)NEX * HDIM);
        scatter_add<<<scat_blocks, 256>>>(hw[cur], near_s, near_d, a0);
        scatter_add<<<scat_blocks, 256>>>(he[cur], refer_s, refer_d, a1);
        scatter_add<<<scat_blocks, 256>>>(he[cur], close_s, close_d, a2);

        // Wr_near + Wr_refer (both act on the same x_dst = h_win)
        wsum_add<<<(HDIM * HDIM + 255) / 256, 256>>>(WrN, WrR, wsum, HDIM * HDIM);

        // window update: hw_next = lrelu(0.5*(rn*a0@WlN + bN + rr*a1@WlR + bR + hw@(WrN+WrR)))
        gemm_launch(NWIN, HDIM, HDIM, a0, WlN, nullptr, tmp, bN, rn, 0.f, 1.f, 0);
        gemm_launch(NWIN, HDIM, HDIM, a1, WlR, tmp, tmp, bR, rr, 1.f, 1.f, 0);
        gemm_launch(NWIN, HDIM, HDIM, hw[cur], wsum, tmp, hw[nxt], nullptr, nullptr, 1.f, 0.5f, 1);

        // example update: he_next = lrelu(rc*a2@WlC + bC + he@WrC)
        gemm_launch(NEX, HDIM, HDIM, a2, WlC, nullptr, tmp, bC, rc, 0.f, 1.f, 0);
        gemm_launch(NEX, HDIM, HDIM, he[cur], WrC, tmp, he[nxt], nullptr, nullptr, 1.f, 1.f, 1);

        cur = nxt;
    }

    // --- CSRA pooling over refer edges into window nodes ---
    gemv_score<<<(NEX + 7) / 8, 256>>>(he[cur], w_pool, score);
    init_mx<<<(NWIN + 255) / 256, 256>>>(mxu, NWIN);
    zero_buf(z, NWIN);
    edge_max<<<edge_blocks, 256>>>(score, refer_s, refer_d, mxu);
    edge_exp<<<edge_blocks, 256>>>(score, refer_s, refer_d, mxu, z, ex);
    edge_norm<<<edge_blocks, 256>>>(refer_d, z, ex);
    zero_buf(a0, (long long)NWIN * HDIM);  // reuse a0 as pooled
    pool_scatter<<<scat_blocks, 256>>>(he[cur], refer_s, refer_d, ex, a0);

    // out = (hw + 0.5*pooled) @ W_lin + b_lin
    addmix<<<(unsigned)(((long long)NWIN * HDIM / 4 + 255) / 256), 256>>>(
        hw[cur], a0, tmp, (long long)NWIN * HDIM / 4);
    gemm_launch(NWIN, NOUT, HDIM, tmp, W_lin, nullptr, out, b_lin, nullptr, 0.f, 1.f, 0);
}

// round 3
// speedup vs baseline: 1.8187x; 1.8187x over previous
#include <cuda_runtime.h>
#include <cuda_bf16.h>
#include <float.h>
#include <math.h>
#include <stdint.h>

#define NWIN 30000
#define NEX  30000
#define EDG  480000
#define HDIM 512
#define NLAYERS 4
#define KWIN 1949
#define KEXP 100
#define NOUT 100
#define MP   30080          // 235 * 128, padded row count for A-plane buffers
#define KP_WIN 1984

// ================= fp32 scratch =================
__device__ __align__(256) float g_hw0[NWIN*HDIM];
__device__ __align__(256) float g_hw1[NWIN*HDIM];
__device__ __align__(256) float g_he0[NEX*HDIM];
__device__ __align__(256) float g_he1[NEX*HDIM];
__device__ __align__(256) float g_a0[NWIN*HDIM];
__device__ __align__(256) float g_a1[NWIN*HDIM];
__device__ __align__(256) float g_a2[NEX*HDIM];
__device__ __align__(256) float g_tmp[NWIN*HDIM];
__device__ float g_rn[NWIN];
__device__ float g_rr[NWIN];
__device__ float g_rc[NEX];
__device__ float g_score[NEX];
__device__ unsigned g_mxu[NWIN];
__device__ float g_z[NWIN];
__device__ float g_ex[EDG];
__device__ float g_bsum[NLAYERS*HDIM];

// ================= bf16 weight buffers [N][Kp], hi & lo planes =================
#define WOFF_STEP   (HDIM*HDIM)
#define WOFF_LAYER  (5*WOFF_STEP)
#define WOFF_WLN(l) ((l)*WOFF_LAYER + 0*WOFF_STEP)
#define WOFF_WLR(l) ((l)*WOFF_LAYER + 1*WOFF_STEP)
#define WOFF_WSUM(l)((l)*WOFF_LAYER + 2*WOFF_STEP)
#define WOFF_WLC(l) ((l)*WOFF_LAYER + 3*WOFF_STEP)
#define WOFF_WRC(l) ((l)*WOFF_LAYER + 4*WOFF_STEP)
#define WOFF_POST   (NLAYERS*WOFF_LAYER)
#define WOFF_WIN    (WOFF_POST + WOFF_STEP)
#define WOFF_EXP    (WOFF_WIN + HDIM*KP_WIN)
#define WOFF_LIN    (WOFF_EXP + HDIM*128)
#define WTOTAL      (WOFF_LIN + 128*HDIM)
__device__ __align__(256) __nv_bfloat16 g_wth[WTOTAL];
__device__ __align__(256) __nv_bfloat16 g_wtl[WTOTAL];

// ================= bf16 activation plane buffers [MP][Kp] =================
__device__ __align__(256) __nv_bfloat16 g_bigh[(size_t)MP*KP_WIN];
__device__ __align__(256) __nv_bfloat16 g_bigl[(size_t)MP*KP_WIN];
__device__ __align__(256) __nv_bfloat16 g_s0h[(size_t)MP*HDIM];
__device__ __align__(256) __nv_bfloat16 g_s0l[(size_t)MP*HDIM];
__device__ __align__(256) __nv_bfloat16 g_s1h[(size_t)MP*HDIM];
__device__ __align__(256) __nv_bfloat16 g_s1l[(size_t)MP*HDIM];
__device__ __align__(256) __nv_bfloat16 g_s2h[(size_t)MP*HDIM];
__device__ __align__(256) __nv_bfloat16 g_s2l[(size_t)MP*HDIM];

// ================= conversion kernels =================
// weights: out[n*Kp + k] = split(W[k*N + n] (+W2)), zero-padded
__global__ void conv_w(const float* __restrict__ W, const float* __restrict__ W2,
                       int K, int N, int Kp,
                       __nv_bfloat16* __restrict__ oh, __nv_bfloat16* __restrict__ ol)
{
    __shared__ float t[32][33];
    int k0 = blockIdx.x * 32, n0 = blockIdx.y * 32;
    int tx = threadIdx.x, ty = threadIdx.y;
#pragma unroll
    for (int i = 0; i < 4; i++) {
        int k = k0 + ty + i * 8, n = n0 + tx;
        float v = 0.f;
        if (k < K && n < N) {
            v = W[(size_t)k * N + n];
            if (W2) v += W2[(size_t)k * N + n];
        }
        t[ty + i * 8][tx] = v;
    }
    __syncthreads();
#pragma unroll
    for (int i = 0; i < 4; i++) {
        int n = n0 + ty + i * 8, k = k0 + tx;
        float v = t[tx][ty + i * 8];
        __nv_bfloat16 hb = __float2bfloat16_rn(v);
        __nv_bfloat16 lb = __float2bfloat16_rn(v - __bfloat162float(hb));
        oh[(size_t)n * Kp + k] = hb;
        ol[(size_t)n * Kp + k] = lb;
    }
}

// activations: out[m*Kp + k] = split(rs[m]*A[m*K + k]), zero-padded rows/cols
__global__ void conv_a(const float* __restrict__ A, const float* __restrict__ rs,
                       int M, int K, int Kp, long long total,
                       __nv_bfloat16* __restrict__ oh, __nv_bfloat16* __restrict__ ol)
{
    long long i = (long long)blockIdx.x * blockDim.x + threadIdx.x;
    if (i >= total) return;
    int m = (int)(i / Kp);
    int k = (int)(i % Kp);
    float v = 0.f;
    if (m < M && k < K) {
        v = A[(size_t)m * K + k];
        if (rs) v *= rs[m];
    }
    __nv_bfloat16 hb = __float2bfloat16_rn(v);
    __nv_bfloat16 lb = __float2bfloat16_rn(v - __bfloat162float(hb));
    oh[i] = hb;
    ol[i] = lb;
}

__global__ void bias_sum(const float* a, const float* b, float* o, int n)
{
    int i = blockIdx.x * blockDim.x + threadIdx.x;
    if (i < n) o[i] = a[i] + b[i];
}

// ================= mma.sync bf16 GEMM =================
// D[M,Nstore] = act(ps*( sum_o Ao@Bo^T + bias[n] ))
// A planes [MP][Kp] bf16 (hi/lo), B planes [Np][Kp] bf16 (hi/lo).
// 3-pass split: hh + hl + lh.
struct GemmArgs {
    const __nv_bfloat16 *Ah[3], *Al[3], *Bh[3], *Bl[3];
    int Kp[3];
    int nops, totChunks;
    int M, Nstore, ldd;
    const float* bias;
    float ps;
    int act;
    float* D;
};

#define STAGE_BYTES 65536   // 4 planes * 16KB (128 rows x 128B)
#define GEMM_SMEM   (2 * STAGE_BYTES)

__device__ __forceinline__ uint32_t smem_u32(const void* p) {
    uint32_t a;
    asm("{ .reg .u64 t; cvta.to.shared.u64 t, %1; cvt.u32.u64 %0, t; }" : "=r"(a) : "l"(p));
    return a;
}
__device__ __forceinline__ void cp16(uint32_t dst, const void* src) {
    asm volatile("cp.async.cg.shared.global [%0], [%1], 16;" :: "r"(dst), "l"(src));
}
__device__ __forceinline__ void cp_commit() { asm volatile("cp.async.commit_group;"); }
__device__ __forceinline__ void cp_wait0() { asm volatile("cp.async.wait_group 0;"); }
__device__ __forceinline__ void cp_wait1() { asm volatile("cp.async.wait_group 1;"); }

__device__ __forceinline__ void ldm_x4(uint32_t* r, uint32_t addr) {
    asm volatile("ldmatrix.sync.aligned.m8n8.x4.shared.b16 {%0,%1,%2,%3}, [%4];"
                 : "=r"(r[0]), "=r"(r[1]), "=r"(r[2]), "=r"(r[3]) : "r"(addr));
}
__device__ __forceinline__ void mma16816(float* c, const uint32_t* a, const uint32_t* b) {
    asm volatile("mma.sync.aligned.m16n8k16.row.col.f32.bf16.bf16.f32 "
                 "{%0,%1,%2,%3},{%4,%5,%6,%7},{%8,%9},{%0,%1,%2,%3};"
                 : "+f"(c[0]), "+f"(c[1]), "+f"(c[2]), "+f"(c[3])
                 : "r"(a[0]), "r"(a[1]), "r"(a[2]), "r"(a[3]), "r"(b[0]), "r"(b[1]));
}

__device__ __forceinline__ void map_oc(const GemmArgs& g, int t, int& o, int& c) {
    o = 0;
    int rem = t;
    while (o < g.nops - 1 && rem >= (g.Kp[o] >> 6)) { rem -= (g.Kp[o] >> 6); o++; }
    c = rem;
}

// load one 64-K chunk (4 planes of 128x64 bf16) into stage s
__device__ __forceinline__ void load_stage(const GemmArgs& g, int t, uint32_t sb,
                                           int tid, int m0, int n0)
{
    int o, c;
    map_oc(g, t, o, c);
    const int Kp = g.Kp[o];
    const int k0 = c << 6;
    const __nv_bfloat16* srcs[4] = { g.Ah[o], g.Al[o], g.Bh[o], g.Bl[o] };
#pragma unroll
    for (int p = 0; p < 4; p++) {
        const int row0 = (p < 2) ? m0 : n0;
        const __nv_bfloat16* base = srcs[p] + (size_t)row0 * Kp + k0;
        uint32_t pb = sb + p * 16384;
#pragma unroll
        for (int it = 0; it < 4; it++) {
            int idx = it * 256 + tid;
            int r = idx >> 3;
            int j = idx & 7;
            uint32_t dst = pb + r * 128 + ((j ^ (r & 7)) << 4);
            cp16(dst, base + (size_t)r * Kp + j * 8);
        }
    }
    cp_commit();
}

__global__ __launch_bounds__(256, 1) void gemm_mma(const __grid_constant__ GemmArgs g)
{
    extern __shared__ __align__(128) char smem[];
    const uint32_t sbase = smem_u32(smem);
    const int tid = threadIdx.x;
    const int lane = tid & 31;
    const int warp = tid >> 5;
    const int wm = warp >> 2;       // 0..1
    const int wn = warp & 3;        // 0..3
    const int m0 = blockIdx.y * 128;
    const int n0 = blockIdx.x * 128;

    float acc[4][4][4];
#pragma unroll
    for (int i = 0; i < 4; i++)
#pragma unroll
        for (int j = 0; j < 4; j++)
#pragma unroll
            for (int q = 0; q < 4; q++) acc[i][j][q] = 0.f;

    // per-thread ldmatrix lane constants
    const int sx = lane & 7;
    const int arow = (lane & 7) + ((lane >> 3) & 1) * 8;  // A: g0/g2 -> +0, g1/g3 -> +8
    const int khia = (lane >> 4) & 1;                     // A: g2,g3 -> k-high
    const int brow = (lane & 7) + ((lane >> 4) & 1) * 8;  // B: g2,g3 -> +8
    const int khib = (lane >> 3) & 1;                     // B: g1,g3 -> k-high

    const int T = g.totChunks;
    load_stage(g, 0, sbase, tid, m0, n0);

    for (int t = 0; t < T; t++) {
        if (t + 1 < T) {
            load_stage(g, t + 1, sbase + ((t + 1) & 1) * STAGE_BYTES, tid, m0, n0);
            cp_wait1();
        } else {
            cp_wait0();
        }
        __syncthreads();

        const uint32_t Ah = sbase + (t & 1) * STAGE_BYTES;
        const uint32_t Al = Ah + 16384;
        const uint32_t Bh = Ah + 32768;
        const uint32_t Bl = Ah + 49152;

#pragma unroll
        for (int ks = 0; ks < 4; ks++) {
            uint32_t ah[4][4], al[4][4], bh[2][4], bl[2][4];
            const uint32_t colA = (uint32_t)(((ks * 2 + khia) ^ sx) << 4);
            const uint32_t colB = (uint32_t)(((ks * 2 + khib) ^ sx) << 4);
#pragma unroll
            for (int mt = 0; mt < 4; mt++) {
                int row = wm * 64 + mt * 16 + arow;
                ldm_x4(ah[mt], Ah + row * 128 + colA);
                ldm_x4(al[mt], Al + row * 128 + colA);
            }
#pragma unroll
            for (int np = 0; np < 2; np++) {
                int row = wn * 32 + np * 16 + brow;
                ldm_x4(bh[np], Bh + row * 128 + colB);
                ldm_x4(bl[np], Bl + row * 128 + colB);
            }
#pragma unroll
            for (int mt = 0; mt < 4; mt++) {
#pragma unroll
                for (int nt = 0; nt < 4; nt++) {
                    const uint32_t* bhf = &bh[nt >> 1][(nt & 1) * 2];
                    const uint32_t* blf = &bl[nt >> 1][(nt & 1) * 2];
                    mma16816(acc[mt][nt], ah[mt], bhf);   // hi*hi
                    mma16816(acc[mt][nt], ah[mt], blf);   // hi*lo
                    mma16816(acc[mt][nt], al[mt], bhf);   // lo*hi
                }
            }
        }
        __syncthreads();
    }

    // ---- epilogue ----
#pragma unroll
    for (int mt = 0; mt < 4; mt++) {
        int row0 = m0 + wm * 64 + mt * 16 + (lane >> 2);
#pragma unroll
        for (int nt = 0; nt < 4; nt++) {
            int col = n0 + wn * 32 + nt * 8 + (lane & 3) * 2;
            if (col >= g.Nstore) continue;
            float b0 = 0.f, b1 = 0.f;
            if (g.bias) {
                b0 = g.bias[col];
                if (col + 1 < g.Nstore) b1 = g.bias[col + 1];
            }
#pragma unroll
            for (int rr = 0; rr < 2; rr++) {
                int r = row0 + rr * 8;
                if (r >= g.M) continue;
                float v0 = (acc[mt][nt][rr * 2 + 0] + b0) * g.ps;
                float v1 = (acc[mt][nt][rr * 2 + 1] + b1) * g.ps;
                if (g.act) {
                    v0 = v0 > 0.f ? v0 : 0.2f * v0;
                    v1 = v1 > 0.f ? v1 : 0.2f * v1;
                }
                float* dp = g.D + (size_t)r * g.ldd + col;
                if (col + 1 < g.Nstore) {
                    *(float2*)dp = make_float2(v0, v1);
                } else {
                    *dp = v0;
                }
            }
        }
    }
}

// ================= elementwise / scatter kernels =================
__global__ void zero_kernel(float* __restrict__ p, long long n4)
{
    long long i = (long long)blockIdx.x * blockDim.x + threadIdx.x;
    if (i < n4) ((float4*)p)[i] = make_float4(0.f, 0.f, 0.f, 0.f);
}
__global__ void count_deg(const int* __restrict__ ed, float* __restrict__ cnt, int n)
{
    int e = blockIdx.x * blockDim.x + threadIdx.x;
    if (e < n) atomicAdd(&cnt[ed[e]], 1.f);
}
__global__ void recip_kernel(float* __restrict__ c, int n)
{
    int i = blockIdx.x * blockDim.x + threadIdx.x;
    if (i < n) c[i] = 1.f / fmaxf(c[i], 1.f);
}
__global__ void scatter_add(const float* __restrict__ src,
                            const int* __restrict__ es,
                            const int* __restrict__ ed,
                            float* __restrict__ out)
{
    long long idx = (long long)blockIdx.x * blockDim.x + threadIdx.x;
    const long long tot = (long long)EDG * (HDIM / 4);
    if (idx >= tot) return;
    int e = (int)(idx >> 7);
    int c = (int)(idx & 127);
    int s = es[e], d = ed[e];
    float4 v = ((const float4*)(src + (size_t)s * HDIM))[c];
    float* o = out + (size_t)d * HDIM + c * 4;
    atomicAdd(o + 0, v.x);
    atomicAdd(o + 1, v.y);
    atomicAdd(o + 2, v.z);
    atomicAdd(o + 3, v.w);
}
__global__ void gemv_score(const float* __restrict__ he, const float* __restrict__ w,
                           float* __restrict__ sc)
{
    int row = blockIdx.x * 8 + (threadIdx.x >> 5);
    if (row >= NEX) return;
    int lane = threadIdx.x & 31;
    const float* r = he + (size_t)row * HDIM;
    float s = 0.f;
#pragma unroll
    for (int k = lane; k < HDIM; k += 32) s += r[k] * w[k];
#pragma unroll
    for (int o = 16; o; o >>= 1) s += __shfl_down_sync(0xFFFFFFFFu, s, o);
    if (lane == 0) sc[row] = s;
}
__device__ __forceinline__ unsigned f2ord(float f)
{
    unsigned u = __float_as_uint(f);
    return (u & 0x80000000u) ? ~u : (u | 0x80000000u);
}
__device__ __forceinline__ float ord2f(unsigned u)
{
    return __uint_as_float((u & 0x80000000u) ? (u & 0x7FFFFFFFu) : ~u);
}
__global__ void init_mx(unsigned* __restrict__ mxu, int n)
{
    int i = blockIdx.x * blockDim.x + threadIdx.x;
    if (i < n) mxu[i] = f2ord(-FLT_MAX);
}
__global__ void edge_max(const float* __restrict__ score, const int* __restrict__ es,
                         const int* __restrict__ ed, unsigned* __restrict__ mxu)
{
    int e = blockIdx.x * blockDim.x + threadIdx.x;
    if (e >= EDG) return;
    atomicMax(&mxu[ed[e]], f2ord(score[es[e]]));
}
__global__ void edge_exp(const float* __restrict__ score, const int* __restrict__ es,
                         const int* __restrict__ ed, const unsigned* __restrict__ mxu,
                         float* __restrict__ z, float* __restrict__ ex)
{
    int e = blockIdx.x * blockDim.x + threadIdx.x;
    if (e >= EDG) return;
    float s = score[es[e]];
    float m = ord2f(mxu[ed[e]]);
    float v = expf(s - m);
    ex[e] = v;
    atomicAdd(&z[ed[e]], v);
}
__global__ void edge_norm(const int* __restrict__ ed, const float* __restrict__ z,
                          float* __restrict__ ex)
{
    int e = blockIdx.x * blockDim.x + threadIdx.x;
    if (e >= EDG) return;
    ex[e] = ex[e] / fmaxf(z[ed[e]], 1e-12f);
}
__global__ void pool_scatter(const float* __restrict__ he, const int* __restrict__ es,
                             const int* __restrict__ ed, const float* __restrict__ w,
                             float* __restrict__ out)
{
    long long idx = (long long)blockIdx.x * blockDim.x + threadIdx.x;
    const long long tot = (long long)EDG * (HDIM / 4);
    if (idx >= tot) return;
    int e = (int)(idx >> 7);
    int c = (int)(idx & 127);
    int s = es[e], d = ed[e];
    float we = w[e];
    float4 v = ((const float4*)(he + (size_t)s * HDIM))[c];
    float* o = out + (size_t)d * HDIM + c * 4;
    atomicAdd(o + 0, we * v.x);
    atomicAdd(o + 1, we * v.y);
    atomicAdd(o + 2, we * v.z);
    atomicAdd(o + 3, we * v.w);
}
__global__ void addmix(const float* __restrict__ hw, const float* __restrict__ pool,
                       float* __restrict__ o, long long n4)
{
    long long i = (long long)blockIdx.x * blockDim.x + threadIdx.x;
    if (i >= n4) return;
    float4 a = ((const float4*)hw)[i];
    float4 b = ((const float4*)pool)[i];
    ((float4*)o)[i] = make_float4(a.x + 0.5f * b.x, a.y + 0.5f * b.y,
                                  a.z + 0.5f * b.z, a.w + 0.5f * b.w);
}

// ================= host orchestration =================
struct OpDesc {
    const __nv_bfloat16 *Ah, *Al, *Bh, *Bl;
    int Kp;
};

static void launch_gemm(const OpDesc* ops, int nops, int M, int Np, int Nstore,
                        int ldd, const float* bias, float ps, int act, float* D)
{
    GemmArgs g;
    int T = 0;
    for (int o = 0; o < nops; o++) {
        g.Ah[o] = ops[o].Ah; g.Al[o] = ops[o].Al;
        g.Bh[o] = ops[o].Bh; g.Bl[o] = ops[o].Bl;
        g.Kp[o] = ops[o].Kp;
        T += ops[o].Kp / 64;
    }
    g.nops = nops; g.totChunks = T;
    g.M = M; g.Nstore = Nstore; g.ldd = ldd;
    g.bias = bias; g.ps = ps; g.act = act; g.D = D;
    dim3 grid(Np / 128, (M + 127) / 128);
    gemm_mma<<<grid, 256, GEMM_SMEM>>>(g);
}

static void launch_conv_a(const float* A, const float* rs, int M, int K, int Kp,
                          __nv_bfloat16* oh, __nv_bfloat16* ol)
{
    long long total = (long long)MP * Kp;
    conv_a<<<(unsigned)((total + 255) / 256), 256>>>(A, rs, M, K, Kp, total, oh, ol);
}

extern "C" void kernel_launch(void* const* d_in, const int* in_sizes, int n_in,
                              void* d_out, int out_size)
{
    const float* x_window  = (const float*)d_in[0];
    const float* x_example = (const float*)d_in[1];
    const int*   e_near    = (const int*)d_in[2];
    const int*   e_close   = (const int*)d_in[3];
    const int*   e_refer   = (const int*)d_in[4];
    const float* W_win     = (const float*)d_in[5];
    const float* W_exp     = (const float*)d_in[6];
    const float* W_post    = (const float*)d_in[7];
    const float* Wl_near   = (const float*)d_in[9];
    const float* Wr_near   = (const float*)d_in[10];
    const float* b_near    = (const float*)d_in[11];
    const float* Wl_close  = (const float*)d_in[12];
    const float* Wr_close  = (const float*)d_in[13];
    const float* b_close   = (const float*)d_in[14];
    const float* Wl_refer  = (const float*)d_in[15];
    const float* Wr_refer  = (const float*)d_in[16];
    const float* b_refer   = (const float*)d_in[17];
    const float* w_pool    = (const float*)d_in[18];
    const float* W_lin     = (const float*)d_in[19];
    const float* b_lin     = (const float*)d_in[20];
    float* out = (float*)d_out;

    cudaFuncSetAttribute(gemm_mma, cudaFuncAttributeMaxDynamicSharedMemorySize, GEMM_SMEM);

    float *hw[2], *he[2], *a0, *a1, *a2, *tmp, *rn, *rr, *rc, *score, *z, *ex, *bsum;
    unsigned* mxu;
    __nv_bfloat16 *wth, *wtl, *bigh, *bigl, *s0h, *s0l, *s1h, *s1l, *s2h, *s2l;
    cudaGetSymbolAddress((void**)&hw[0], g_hw0);
    cudaGetSymbolAddress((void**)&hw[1], g_hw1);
    cudaGetSymbolAddress((void**)&he[0], g_he0);
    cudaGetSymbolAddress((void**)&he[1], g_he1);
    cudaGetSymbolAddress((void**)&a0, g_a0);
    cudaGetSymbolAddress((void**)&a1, g_a1);
    cudaGetSymbolAddress((void**)&a2, g_a2);
    cudaGetSymbolAddress((void**)&tmp, g_tmp);
    cudaGetSymbolAddress((void**)&rn, g_rn);
    cudaGetSymbolAddress((void**)&rr, g_rr);
    cudaGetSymbolAddress((void**)&rc, g_rc);
    cudaGetSymbolAddress((void**)&score, g_score);
    cudaGetSymbolAddress((void**)&mxu, g_mxu);
    cudaGetSymbolAddress((void**)&z, g_z);
    cudaGetSymbolAddress((void**)&ex, g_ex);
    cudaGetSymbolAddress((void**)&bsum, g_bsum);
    cudaGetSymbolAddress((void**)&wth, g_wth);
    cudaGetSymbolAddress((void**)&wtl, g_wtl);
    cudaGetSymbolAddress((void**)&bigh, g_bigh);
    cudaGetSymbolAddress((void**)&bigl, g_bigl);
    cudaGetSymbolAddress((void**)&s0h, g_s0h);
    cudaGetSymbolAddress((void**)&s0l, g_s0l);
    cudaGetSymbolAddress((void**)&s1h, g_s1h);
    cudaGetSymbolAddress((void**)&s1l, g_s1l);
    cudaGetSymbolAddress((void**)&s2h, g_s2h);
    cudaGetSymbolAddress((void**)&s2l, g_s2l);

    const int* near_s = e_near;   const int* near_d = e_near + EDG;
    const int* close_s = e_close; const int* close_d = e_close + EDG;
    const int* refer_s = e_refer; const int* refer_d = e_refer + EDG;

    const long long scat_tot = (long long)EDG * (HDIM / 4);
    const unsigned scat_blocks = (unsigned)((scat_tot + 255) / 256);
    const unsigned edge_blocks = (EDG + 255) / 256;
    const long long nh4 = (long long)NWIN * HDIM / 4;

    // --- weight conversion ---
    {
        dim3 blk(32, 8);
        dim3 gHH(HDIM / 32, HDIM / 32);
        for (int l = 0; l < NLAYERS; l++) {
            size_t s = (size_t)l * HDIM * HDIM;
            conv_w<<<gHH, blk>>>(Wl_near + s, nullptr, HDIM, HDIM, HDIM, wth + WOFF_WLN(l), wtl + WOFF_WLN(l));
            conv_w<<<gHH, blk>>>(Wl_refer + s, nullptr, HDIM, HDIM, HDIM, wth + WOFF_WLR(l), wtl + WOFF_WLR(l));
            conv_w<<<gHH, blk>>>(Wr_near + s, Wr_refer + s, HDIM, HDIM, HDIM, wth + WOFF_WSUM(l), wtl + WOFF_WSUM(l));
            conv_w<<<gHH, blk>>>(Wl_close + s, nullptr, HDIM, HDIM, HDIM, wth + WOFF_WLC(l), wtl + WOFF_WLC(l));
            conv_w<<<gHH, blk>>>(Wr_close + s, nullptr, HDIM, HDIM, HDIM, wth + WOFF_WRC(l), wtl + WOFF_WRC(l));
            bias_sum<<<(HDIM + 255) / 256, 256>>>(b_near + (size_t)l * HDIM, b_refer + (size_t)l * HDIM,
                                                  bsum + (size_t)l * HDIM, HDIM);
        }
        conv_w<<<gHH, blk>>>(W_post, nullptr, HDIM, HDIM, HDIM, wth + WOFF_POST, wtl + WOFF_POST);
        dim3 gWIN(KP_WIN / 32, HDIM / 32);
        conv_w<<<gWIN, blk>>>(W_win, nullptr, KWIN, HDIM, KP_WIN, wth + WOFF_WIN, wtl + WOFF_WIN);
        dim3 gEXP(128 / 32, HDIM / 32);
        conv_w<<<gEXP, blk>>>(W_exp, nullptr, KEXP, HDIM, 128, wth + WOFF_EXP, wtl + WOFF_EXP);
        dim3 gLIN(HDIM / 32, 128 / 32);
        conv_w<<<gLIN, blk>>>(W_lin, nullptr, HDIM, NOUT, HDIM, wth + WOFF_LIN, wtl + WOFF_LIN);
    }

    // --- degree reciprocals ---
    zero_kernel<<<(NWIN / 4 + 255) / 256, 256>>>(rn, NWIN / 4);
    zero_kernel<<<(NWIN / 4 + 255) / 256, 256>>>(rr, NWIN / 4);
    zero_kernel<<<(NEX / 4 + 255) / 256, 256>>>(rc, NEX / 4);
    count_deg<<<edge_blocks, 256>>>(near_d, rn, EDG);
    count_deg<<<edge_blocks, 256>>>(refer_d, rr, EDG);
    count_deg<<<edge_blocks, 256>>>(close_d, rc, EDG);
    recip_kernel<<<(NWIN + 255) / 256, 256>>>(rn, NWIN);
    recip_kernel<<<(NWIN + 255) / 256, 256>>>(rr, NWIN);
    recip_kernel<<<(NEX + 255) / 256, 256>>>(rc, NEX);

    // --- input projections: h = lrelu(lrelu(x@W)@W_post) ---
    {
        launch_conv_a(x_example, nullptr, NEX, KEXP, 128, s0h, s0l);
        OpDesc op = { s0h, s0l, wth + WOFF_EXP, wtl + WOFF_EXP, 128 };
        launch_gemm(&op, 1, NEX, HDIM, HDIM, HDIM, nullptr, 1.f, 1, tmp);
        launch_conv_a(tmp, nullptr, NEX, HDIM, HDIM, s0h, s0l);
        op = { s0h, s0l, wth + WOFF_POST, wtl + WOFF_POST, HDIM };
        launch_gemm(&op, 1, NEX, HDIM, HDIM, HDIM, nullptr, 1.f, 1, he[0]);

        launch_conv_a(x_window, nullptr, NWIN, KWIN, KP_WIN, bigh, bigl);
        op = { bigh, bigl, wth + WOFF_WIN, wtl + WOFF_WIN, KP_WIN };
        launch_gemm(&op, 1, NWIN, HDIM, HDIM, HDIM, nullptr, 1.f, 1, tmp);
        launch_conv_a(tmp, nullptr, NWIN, HDIM, HDIM, s0h, s0l);
        op = { s0h, s0l, wth + WOFF_POST, wtl + WOFF_POST, HDIM };
        launch_gemm(&op, 1, NWIN, HDIM, HDIM, HDIM, nullptr, 1.f, 1, hw[0]);
    }

    // --- SAGE layers ---
    int cur = 0;
    for (int l = 0; l < NLAYERS; l++) {
        int nxt = cur ^ 1;
        zero_kernel<<<(unsigned)((nh4 + 255) / 256), 256>>>(a0, nh4);
        zero_kernel<<<(unsigned)((nh4 + 255) / 256), 256>>>(a1, nh4);
        zero_kernel<<<(unsigned)((nh4 + 255) / 256), 256>>>(a2, nh4);
        scatter_add<<<scat_blocks, 256>>>(hw[cur], near_s, near_d, a0);
        scatter_add<<<scat_blocks, 256>>>(he[cur], refer_s, refer_d, a1);
        scatter_add<<<scat_blocks, 256>>>(he[cur], close_s, close_d, a2);

        // window: lrelu(0.5*(rn*a0@WlN + rr*a1@WlR + hw@(WrN+WrR) + bN+bR))
        launch_conv_a(a0, rn, NWIN, HDIM, HDIM, s0h, s0l);
        launch_conv_a(a1, rr, NWIN, HDIM, HDIM, s1h, s1l);
        launch_conv_a(hw[cur], nullptr, NWIN, HDIM, HDIM, s2h, s2l);
        OpDesc ops3[3] = {
            { s0h, s0l, wth + WOFF_WLN(l), wtl + WOFF_WLN(l), HDIM },
            { s1h, s1l, wth + WOFF_WLR(l), wtl + WOFF_WLR(l), HDIM },
            { s2h, s2l, wth + WOFF_WSUM(l), wtl + WOFF_WSUM(l), HDIM },
        };
        launch_gemm(ops3, 3, NWIN, HDIM, HDIM, HDIM, bsum + (size_t)l * HDIM, 0.5f, 1, hw[nxt]);

        // example: lrelu(rc*a2@WlC + he@WrC + bC)
        launch_conv_a(a2, rc, NEX, HDIM, HDIM, s0h, s0l);
        launch_conv_a(he[cur], nullptr, NEX, HDIM, HDIM, s1h, s1l);
        OpDesc ops2[2] = {
            { s0h, s0l, wth + WOFF_WLC(l), wtl + WOFF_WLC(l), HDIM },
            { s1h, s1l, wth + WOFF_WRC(l), wtl + WOFF_WRC(l), HDIM },
        };
        launch_gemm(ops2, 2, NEX, HDIM, HDIM, HDIM, b_close + (size_t)l * HDIM, 1.f, 1, he[nxt]);
        cur = nxt;
    }

    // --- CSRA pooling over refer edges into window nodes ---
    gemv_score<<<(NEX + 7) / 8, 256>>>(he[cur], w_pool, score);
    init_mx<<<(NWIN + 255) / 256, 256>>>(mxu, NWIN);
    zero_kernel<<<(NWIN / 4 + 255) / 256, 256>>>(z, NWIN / 4);
    edge_max<<<edge_blocks, 256>>>(score, refer_s, refer_d, mxu);
    edge_exp<<<edge_blocks, 256>>>(score, refer_s, refer_d, mxu, z, ex);
    edge_norm<<<edge_blocks, 256>>>(refer_d, z, ex);
    zero_kernel<<<(unsigned)((nh4 + 255) / 256), 256>>>(a0, nh4);
    pool_scatter<<<scat_blocks, 256>>>(he[cur], refer_s, refer_d, ex, a0);

    // out = (hw + 0.5*pooled) @ W_lin + b_lin
    addmix<<<(unsigned)((nh4 + 255) / 256), 256>>>(hw[cur], a0, tmp, nh4);
    launch_conv_a(tmp, nullptr, NWIN, HDIM, HDIM, s0h, s0l);
    OpDesc opf = { s0h, s0l, wth + WOFF_LIN, wtl + WOFF_LIN, HDIM };
    launch_gemm(&opf, 1, NWIN, 128, NOUT, NOUT, b_lin, 1.f, 0, out);
}

// round 4
// speedup vs baseline: 4.6682x; 2.5668x over previous
#include <cuda_runtime.h>
#include <cuda_bf16.h>
#include <float.h>
#include <math.h>
#include <stdint.h>

#define NWIN 30000
#define NEX  30000
#define EDG  480000
#define HDIM 512
#define NLAYERS 4
#define KWIN 1949
#define KEXP 100
#define NOUT 100
#define MP   30080          // padded row count (235*128)
#define KP_WIN 1984

// ================= fp32 scratch =================
__device__ __align__(256) float g_hw0[NWIN*HDIM];
__device__ __align__(256) float g_hw1[NWIN*HDIM];
__device__ __align__(256) float g_he0[NEX*HDIM];
__device__ __align__(256) float g_he1[NEX*HDIM];
__device__ float g_score[NEX];
__device__ float g_bsum[NLAYERS*HDIM];

// ================= CSR scratch =================
__device__ int g_cnt[3*NWIN];
__device__ int g_off[3*(NWIN+1)];
__device__ int g_cur[3*NWIN];
__device__ int g_csrc[3*EDG];

// ================= bf16 weight buffers [N][Kp], hi & lo =================
#define WOFF_STEP   (HDIM*HDIM)
#define WOFF_LAYER  (5*WOFF_STEP)
#define WOFF_WLN(l) ((l)*WOFF_LAYER + 0*WOFF_STEP)
#define WOFF_WLR(l) ((l)*WOFF_LAYER + 1*WOFF_STEP)
#define WOFF_WSUM(l)((l)*WOFF_LAYER + 2*WOFF_STEP)
#define WOFF_WLC(l) ((l)*WOFF_LAYER + 3*WOFF_STEP)
#define WOFF_WRC(l) ((l)*WOFF_LAYER + 4*WOFF_STEP)
#define WOFF_POST   (NLAYERS*WOFF_LAYER)
#define WOFF_WIN    (WOFF_POST + WOFF_STEP)
#define WOFF_EXP    (WOFF_WIN + HDIM*KP_WIN)
#define WOFF_LIN    (WOFF_EXP + HDIM*128)
#define WTOTAL      (WOFF_LIN + 128*HDIM)
__device__ __align__(256) __nv_bfloat16 g_wth[WTOTAL];
__device__ __align__(256) __nv_bfloat16 g_wtl[WTOTAL];

// ================= bf16 activation plane buffers =================
__device__ __align__(256) __nv_bfloat16 g_bigh[(size_t)MP*KP_WIN];
__device__ __align__(256) __nv_bfloat16 g_bigl[(size_t)MP*KP_WIN];
__device__ __align__(256) __nv_bfloat16 g_pth[(size_t)MP*HDIM];
__device__ __align__(256) __nv_bfloat16 g_ptl[(size_t)MP*HDIM];
__device__ __align__(256) __nv_bfloat16 g_phw0h[(size_t)MP*HDIM];
__device__ __align__(256) __nv_bfloat16 g_phw0l[(size_t)MP*HDIM];
__device__ __align__(256) __nv_bfloat16 g_phw1h[(size_t)MP*HDIM];
__device__ __align__(256) __nv_bfloat16 g_phw1l[(size_t)MP*HDIM];
__device__ __align__(256) __nv_bfloat16 g_phe0h[(size_t)MP*HDIM];
__device__ __align__(256) __nv_bfloat16 g_phe0l[(size_t)MP*HDIM];
__device__ __align__(256) __nv_bfloat16 g_phe1h[(size_t)MP*HDIM];
__device__ __align__(256) __nv_bfloat16 g_phe1l[(size_t)MP*HDIM];
__device__ __align__(256) __nv_bfloat16 g_pa0h[(size_t)MP*HDIM];
__device__ __align__(256) __nv_bfloat16 g_pa0l[(size_t)MP*HDIM];
__device__ __align__(256) __nv_bfloat16 g_pa1h[(size_t)MP*HDIM];
__device__ __align__(256) __nv_bfloat16 g_pa1l[(size_t)MP*HDIM];
__device__ __align__(256) __nv_bfloat16 g_pa2h[(size_t)MP*HDIM];
__device__ __align__(256) __nv_bfloat16 g_pa2l[(size_t)MP*HDIM];

// ================= helpers =================
__device__ __forceinline__ void split2(float v0, float v1, __nv_bfloat162& h, __nv_bfloat162& l)
{
    __nv_bfloat16 h0 = __float2bfloat16_rn(v0);
    __nv_bfloat16 h1 = __float2bfloat16_rn(v1);
    h.x = h0; h.y = h1;
    l.x = __float2bfloat16_rn(v0 - __bfloat162float(h0));
    l.y = __float2bfloat16_rn(v1 - __bfloat162float(h1));
}

// ================= conversion kernels =================
__global__ void conv_w(const float* __restrict__ W, const float* __restrict__ W2,
                       int K, int N, int Kp,
                       __nv_bfloat16* __restrict__ oh, __nv_bfloat16* __restrict__ ol)
{
    __shared__ float t[32][33];
    int k0 = blockIdx.x * 32, n0 = blockIdx.y * 32;
    int tx = threadIdx.x, ty = threadIdx.y;
#pragma unroll
    for (int i = 0; i < 4; i++) {
        int k = k0 + ty + i * 8, n = n0 + tx;
        float v = 0.f;
        if (k < K && n < N) {
            v = W[(size_t)k * N + n];
            if (W2) v += W2[(size_t)k * N + n];
        }
        t[ty + i * 8][tx] = v;
    }
    __syncthreads();
#pragma unroll
    for (int i = 0; i < 4; i++) {
        int n = n0 + ty + i * 8, k = k0 + tx;
        float v = t[tx][ty + i * 8];
        __nv_bfloat16 hb = __float2bfloat16_rn(v);
        oh[(size_t)n * Kp + k] = hb;
        ol[(size_t)n * Kp + k] = __float2bfloat16_rn(v - __bfloat162float(hb));
    }
}

__global__ void conv_a(const float* __restrict__ A, int M, int K, int Kp, long long total,
                       __nv_bfloat16* __restrict__ oh, __nv_bfloat16* __restrict__ ol)
{
    long long i = (long long)blockIdx.x * blockDim.x + threadIdx.x;
    if (i >= total) return;
    int m = (int)(i / Kp);
    int k = (int)(i % Kp);
    float v = 0.f;
    if (m < M && k < K) v = A[(size_t)m * K + k];
    __nv_bfloat16 hb = __float2bfloat16_rn(v);
    oh[i] = hb;
    ol[i] = __float2bfloat16_rn(v - __bfloat162float(hb));
}

__global__ void bias_sum(const float* a, const float* b, float* o, int n)
{
    int i = blockIdx.x * blockDim.x + threadIdx.x;
    if (i < n) o[i] = a[i] + b[i];
}

__global__ void zero_int(int* p, int n)
{
    int i = blockIdx.x * blockDim.x + threadIdx.x;
    if (i < n) p[i] = 0;
}

// zero pad rows [NWIN, MP) of a plane pair (HDIM cols)
__global__ void zero_pad(__nv_bfloat16* __restrict__ h, __nv_bfloat16* __restrict__ l)
{
    int i = blockIdx.x * blockDim.x + threadIdx.x;
    const int tot = (MP - NWIN) * HDIM;
    if (i < tot) {
        h[(size_t)NWIN * HDIM + i] = __float2bfloat16_rn(0.f);
        l[(size_t)NWIN * HDIM + i] = __float2bfloat16_rn(0.f);
    }
}

// ================= CSR build =================
__global__ void hist_kernel(const int* __restrict__ ed, int* __restrict__ cnt, int n)
{
    int e = blockIdx.x * blockDim.x + threadIdx.x;
    if (e < n) atomicAdd(&cnt[ed[e]], 1);
}

__global__ void scan_kernel(const int* __restrict__ cnt, int* __restrict__ off,
                            int* __restrict__ cur, int n)
{
    __shared__ int s[1024];
    int t = threadIdx.x;
    int chunk = (n + 1023) >> 10;
    int b = t * chunk, e = min(b + chunk, n);
    int sum = 0;
    for (int i = b; i < e; i++) sum += cnt[i];
    s[t] = sum;
    __syncthreads();
    for (int d = 1; d < 1024; d <<= 1) {
        int v = (t >= d) ? s[t - d] : 0;
        __syncthreads();
        s[t] += v;
        __syncthreads();
    }
    int run = (t == 0) ? 0 : s[t - 1];
    for (int i = b; i < e; i++) {
        off[i] = run; cur[i] = run; run += cnt[i];
    }
    if (t == 0) off[n] = s[1023];
}

__global__ void csr_fill(const int* __restrict__ es, const int* __restrict__ ed,
                         int* __restrict__ cur, int* __restrict__ csrc, int n)
{
    int e = blockIdx.x * blockDim.x + threadIdx.x;
    if (e < n) {
        int p = atomicAdd(&cur[ed[e]], 1);
        csrc[p] = es[e];
    }
}

// ================= CSR gather-mean -> bf16 planes =================
// one block (128 thr) per dst row; out[d] = split(mean of src[csrc[e]])
__global__ void gather_mean(const float* __restrict__ src, const int* __restrict__ off,
                            const int* __restrict__ csrc, int ndst,
                            __nv_bfloat16* __restrict__ oh, __nv_bfloat16* __restrict__ ol)
{
    int d = blockIdx.x;
    int t = threadIdx.x;
    float4 acc = make_float4(0.f, 0.f, 0.f, 0.f);
    int deg = 0;
    if (d < ndst) {
        int s0 = off[d], s1 = off[d + 1];
        deg = s1 - s0;
        for (int e = s0; e < s1; e++) {
            float4 v = ((const float4*)(src + (size_t)csrc[e] * HDIM))[t];
            acc.x += v.x; acc.y += v.y; acc.z += v.z; acc.w += v.w;
        }
    }
    float inv = 1.f / (float)max(deg, 1);
    acc.x *= inv; acc.y *= inv; acc.z *= inv; acc.w *= inv;
    __nv_bfloat162 h0, l0, h1, l1;
    split2(acc.x, acc.y, h0, l0);
    split2(acc.z, acc.w, h1, l1);
    size_t o = (size_t)d * HDIM + t * 4;
    *(__nv_bfloat162*)(oh + o) = h0;
    *(__nv_bfloat162*)(oh + o + 2) = h1;
    *(__nv_bfloat162*)(ol + o) = l0;
    *(__nv_bfloat162*)(ol + o + 2) = l1;
}

// ================= CSR softmax pooling: planes = split(hw + 0.5*sum att*he[src]) ====
__global__ void pool_gather(const float* __restrict__ he, const float* __restrict__ hw,
                            const float* __restrict__ score,
                            const int* __restrict__ off, const int* __restrict__ csrc,
                            int ndst,
                            __nv_bfloat16* __restrict__ oh, __nv_bfloat16* __restrict__ ol)
{
    __shared__ float red[128];
    int d = blockIdx.x;
    int t = threadIdx.x;
    float4 res = make_float4(0.f, 0.f, 0.f, 0.f);
    if (d < ndst) {
        int s0 = off[d], s1 = off[d + 1];
        float m = -FLT_MAX;
        for (int e = s0 + t; e < s1; e += 128) m = fmaxf(m, score[csrc[e]]);
        red[t] = m; __syncthreads();
        for (int w = 64; w; w >>= 1) {
            if (t < w) red[t] = fmaxf(red[t], red[t + w]);
            __syncthreads();
        }
        float smax = red[0];
        __syncthreads();
        float z = 0.f;
        for (int e = s0 + t; e < s1; e += 128) z += expf(score[csrc[e]] - smax);
        red[t] = z; __syncthreads();
        for (int w = 64; w; w >>= 1) {
            if (t < w) red[t] += red[t + w];
            __syncthreads();
        }
        float invz = 1.f / fmaxf(red[0], 1e-12f);
        float4 acc = make_float4(0.f, 0.f, 0.f, 0.f);
        for (int e = s0; e < s1; e++) {
            int sidx = csrc[e];
            float w = expf(score[sidx] - smax) * invz;
            float4 v = ((const float4*)(he + (size_t)sidx * HDIM))[t];
            acc.x += w * v.x; acc.y += w * v.y; acc.z += w * v.z; acc.w += w * v.w;
        }
        float4 h = ((const float4*)(hw + (size_t)d * HDIM))[t];
        res.x = h.x + 0.5f * acc.x;
        res.y = h.y + 0.5f * acc.y;
        res.z = h.z + 0.5f * acc.z;
        res.w = h.w + 0.5f * acc.w;
    }
    __nv_bfloat162 h0, l0, h1, l1;
    split2(res.x, res.y, h0, l0);
    split2(res.z, res.w, h1, l1);
    size_t o = (size_t)d * HDIM + t * 4;
    *(__nv_bfloat162*)(oh + o) = h0;
    *(__nv_bfloat162*)(oh + o + 2) = h1;
    *(__nv_bfloat162*)(ol + o) = l0;
    *(__nv_bfloat162*)(ol + o + 2) = l1;
}

// ================= score gemv =================
__global__ void gemv_score(const float* __restrict__ he, const float* __restrict__ w,
                           float* __restrict__ sc)
{
    int row = blockIdx.x * 8 + (threadIdx.x >> 5);
    if (row >= NEX) return;
    int lane = threadIdx.x & 31;
    const float* r = he + (size_t)row * HDIM;
    float s = 0.f;
#pragma unroll
    for (int k = lane; k < HDIM; k += 32) s += r[k] * w[k];
#pragma unroll
    for (int o = 16; o; o >>= 1) s += __shfl_down_sync(0xFFFFFFFFu, s, o);
    if (lane == 0) sc[row] = s;
}

// ================= mma.sync bf16 GEMM (3-pass split) =================
struct GemmArgs {
    const __nv_bfloat16 *Ah[3], *Al[3], *Bh[3], *Bl[3];
    int Kp[3];
    int nops, totChunks;
    int M, Nstore, ldd;
    const float* bias;
    float ps;
    int act;
    float* D;               // nullable fp32 output
    __nv_bfloat16 *Dh, *Dl; // nullable bf16 plane outputs (ld = HDIM)
};

#define STAGE_BYTES 65536
#define GEMM_SMEM   (2 * STAGE_BYTES)

__device__ __forceinline__ uint32_t smem_u32(const void* p) {
    uint32_t a;
    asm("{ .reg .u64 t; cvta.to.shared.u64 t, %1; cvt.u32.u64 %0, t; }" : "=r"(a) : "l"(p));
    return a;
}
__device__ __forceinline__ void cp16(uint32_t dst, const void* src) {
    asm volatile("cp.async.cg.shared.global [%0], [%1], 16;" :: "r"(dst), "l"(src));
}
__device__ __forceinline__ void cp_commit() { asm volatile("cp.async.commit_group;"); }
__device__ __forceinline__ void cp_wait0() { asm volatile("cp.async.wait_group 0;"); }
__device__ __forceinline__ void cp_wait1() { asm volatile("cp.async.wait_group 1;"); }

__device__ __forceinline__ void ldm_x4(uint32_t* r, uint32_t addr) {
    asm volatile("ldmatrix.sync.aligned.m8n8.x4.shared.b16 {%0,%1,%2,%3}, [%4];"
                 : "=r"(r[0]), "=r"(r[1]), "=r"(r[2]), "=r"(r[3]) : "r"(addr));
}
__device__ __forceinline__ void mma16816(float* c, const uint32_t* a, const uint32_t* b) {
    asm volatile("mma.sync.aligned.m16n8k16.row.col.f32.bf16.bf16.f32 "
                 "{%0,%1,%2,%3},{%4,%5,%6,%7},{%8,%9},{%0,%1,%2,%3};"
                 : "+f"(c[0]), "+f"(c[1]), "+f"(c[2]), "+f"(c[3])
                 : "r"(a[0]), "r"(a[1]), "r"(a[2]), "r"(a[3]), "r"(b[0]), "r"(b[1]));
}

__device__ __forceinline__ void map_oc(const GemmArgs& g, int t, int& o, int& c) {
    o = 0;
    int rem = t;
    while (o < g.nops - 1 && rem >= (g.Kp[o] >> 6)) { rem -= (g.Kp[o] >> 6); o++; }
    c = rem;
}

__device__ __forceinline__ void load_stage(const GemmArgs& g, int t, uint32_t sb,
                                           int tid, int m0, int n0)
{
    int o, c;
    map_oc(g, t, o, c);
    const int Kp = g.Kp[o];
    const int k0 = c << 6;
    const __nv_bfloat16* srcs[4] = { g.Ah[o], g.Al[o], g.Bh[o], g.Bl[o] };
#pragma unroll
    for (int p = 0; p < 4; p++) {
        const int row0 = (p < 2) ? m0 : n0;
        const __nv_bfloat16* base = srcs[p] + (size_t)row0 * Kp + k0;
        uint32_t pb = sb + p * 16384;
#pragma unroll
        for (int it = 0; it < 4; it++) {
            int idx = it * 256 + tid;
            int r = idx >> 3;
            int j = idx & 7;
            uint32_t dst = pb + r * 128 + ((j ^ (r & 7)) << 4);
            cp16(dst, base + (size_t)r * Kp + j * 8);
        }
    }
    cp_commit();
}

__global__ __launch_bounds__(256, 1) void gemm_mma(const __grid_constant__ GemmArgs g)
{
    extern __shared__ __align__(128) char smem[];
    const uint32_t sbase = smem_u32(smem);
    const int tid = threadIdx.x;
    const int lane = tid & 31;
    const int warp = tid >> 5;
    const int wm = warp >> 2;
    const int wn = warp & 3;
    const int m0 = blockIdx.y * 128;
    const int n0 = blockIdx.x * 128;

    float acc[4][4][4];
#pragma unroll
    for (int i = 0; i < 4; i++)
#pragma unroll
        for (int j = 0; j < 4; j++)
#pragma unroll
            for (int q = 0; q < 4; q++) acc[i][j][q] = 0.f;

    const int sx = lane & 7;
    const int arow = (lane & 7) + ((lane >> 3) & 1) * 8;
    const int khia = (lane >> 4) & 1;
    const int brow = (lane & 7) + ((lane >> 4) & 1) * 8;
    const int khib = (lane >> 3) & 1;

    const int T = g.totChunks;
    load_stage(g, 0, sbase, tid, m0, n0);

    for (int t = 0; t < T; t++) {
        if (t + 1 < T) {
            load_stage(g, t + 1, sbase + ((t + 1) & 1) * STAGE_BYTES, tid, m0, n0);
            cp_wait1();
        } else {
            cp_wait0();
        }
        __syncthreads();

        const uint32_t Ah = sbase + (t & 1) * STAGE_BYTES;
        const uint32_t Al = Ah + 16384;
        const uint32_t Bh = Ah + 32768;
        const uint32_t Bl = Ah + 49152;

#pragma unroll
        for (int ks = 0; ks < 4; ks++) {
            uint32_t ah[4][4], al[4][4], bh[2][4], bl[2][4];
            const uint32_t colA = (uint32_t)(((ks * 2 + khia) ^ sx) << 4);
            const uint32_t colB = (uint32_t)(((ks * 2 + khib) ^ sx) << 4);
#pragma unroll
            for (int mt = 0; mt < 4; mt++) {
                int row = wm * 64 + mt * 16 + arow;
                ldm_x4(ah[mt], Ah + row * 128 + colA);
                ldm_x4(al[mt], Al + row * 128 + colA);
            }
#pragma unroll
            for (int np = 0; np < 2; np++) {
                int row = wn * 32 + np * 16 + brow;
                ldm_x4(bh[np], Bh + row * 128 + colB);
                ldm_x4(bl[np], Bl + row * 128 + colB);
            }
#pragma unroll
            for (int mt = 0; mt < 4; mt++) {
#pragma unroll
                for (int nt = 0; nt < 4; nt++) {
                    const uint32_t* bhf = &bh[nt >> 1][(nt & 1) * 2];
                    const uint32_t* blf = &bl[nt >> 1][(nt & 1) * 2];
                    mma16816(acc[mt][nt], ah[mt], bhf);
                    mma16816(acc[mt][nt], ah[mt], blf);
                    mma16816(acc[mt][nt], al[mt], bhf);
                }
            }
        }
        __syncthreads();
    }

    // ---- epilogue ----
#pragma unroll
    for (int mt = 0; mt < 4; mt++) {
        int row0 = m0 + wm * 64 + mt * 16 + (lane >> 2);
#pragma unroll
        for (int nt = 0; nt < 4; nt++) {
            int col = n0 + wn * 32 + nt * 8 + (lane & 3) * 2;
            if (col >= g.Nstore) continue;
            float b0 = 0.f, b1 = 0.f;
            if (g.bias) {
                b0 = g.bias[col];
                if (col + 1 < g.Nstore) b1 = g.bias[col + 1];
            }
#pragma unroll
            for (int rr = 0; rr < 2; rr++) {
                int r = row0 + rr * 8;
                if (r >= g.M) continue;
                float v0 = (acc[mt][nt][rr * 2 + 0] + b0) * g.ps;
                float v1 = (acc[mt][nt][rr * 2 + 1] + b1) * g.ps;
                if (g.act) {
                    v0 = v0 > 0.f ? v0 : 0.2f * v0;
                    v1 = v1 > 0.f ? v1 : 0.2f * v1;
                }
                if (g.D) {
                    float* dp = g.D + (size_t)r * g.ldd + col;
                    if (col + 1 < g.Nstore) *(float2*)dp = make_float2(v0, v1);
                    else *dp = v0;
                }
                if (g.Dh) {
                    __nv_bfloat162 hh, ll;
                    split2(v0, v1, hh, ll);
                    size_t po = (size_t)r * HDIM + col;
                    *(__nv_bfloat162*)(g.Dh + po) = hh;
                    *(__nv_bfloat162*)(g.Dl + po) = ll;
                }
            }
        }
    }
}

// ================= host orchestration =================
struct OpDesc {
    const __nv_bfloat16 *Ah, *Al, *Bh, *Bl;
    int Kp;
};

static void launch_gemm(const OpDesc* ops, int nops, int M, int Np, int Nstore,
                        int ldd, const float* bias, float ps, int act,
                        float* D, __nv_bfloat16* Dh, __nv_bfloat16* Dl)
{
    GemmArgs g;
    int T = 0;
    for (int o = 0; o < nops; o++) {
        g.Ah[o] = ops[o].Ah; g.Al[o] = ops[o].Al;
        g.Bh[o] = ops[o].Bh; g.Bl[o] = ops[o].Bl;
        g.Kp[o] = ops[o].Kp;
        T += ops[o].Kp / 64;
    }
    g.nops = nops; g.totChunks = T;
    g.M = M; g.Nstore = Nstore; g.ldd = ldd;
    g.bias = bias; g.ps = ps; g.act = act;
    g.D = D; g.Dh = Dh; g.Dl = Dl;
    dim3 grid(Np / 128, (M + 127) / 128);
    gemm_mma<<<grid, 256, GEMM_SMEM>>>(g);
}

extern "C" void kernel_launch(void* const* d_in, const int* in_sizes, int n_in,
                              void* d_out, int out_size)
{
    const float* x_window  = (const float*)d_in[0];
    const float* x_example = (const float*)d_in[1];
    const int*   e_near    = (const int*)d_in[2];
    const int*   e_close   = (const int*)d_in[3];
    const int*   e_refer   = (const int*)d_in[4];
    const float* W_win     = (const float*)d_in[5];
    const float* W_exp     = (const float*)d_in[6];
    const float* W_post    = (const float*)d_in[7];
    const float* Wl_near   = (const float*)d_in[9];
    const float* Wr_near   = (const float*)d_in[10];
    const float* b_near    = (const float*)d_in[11];
    const float* Wl_close  = (const float*)d_in[12];
    const float* Wr_close  = (const float*)d_in[13];
    const float* b_close   = (const float*)d_in[14];
    const float* Wl_refer  = (const float*)d_in[15];
    const float* Wr_refer  = (const float*)d_in[16];
    const float* b_refer   = (const float*)d_in[17];
    const float* w_pool    = (const float*)d_in[18];
    const float* W_lin     = (const float*)d_in[19];
    const float* b_lin     = (const float*)d_in[20];
    float* out = (float*)d_out;

    cudaFuncSetAttribute(gemm_mma, cudaFuncAttributeMaxDynamicSharedMemorySize, GEMM_SMEM);

    float *hw[2], *he[2], *score, *bsum;
    int *cnt, *off, *cur, *csrc;
    __nv_bfloat16 *wth, *wtl, *bigh, *bigl, *pth, *ptl;
    __nv_bfloat16 *phwh[2], *phwl[2], *pheh[2], *phel[2];
    __nv_bfloat16 *pa0h, *pa0l, *pa1h, *pa1l, *pa2h, *pa2l;
    cudaGetSymbolAddress((void**)&hw[0], g_hw0);
    cudaGetSymbolAddress((void**)&hw[1], g_hw1);
    cudaGetSymbolAddress((void**)&he[0], g_he0);
    cudaGetSymbolAddress((void**)&he[1], g_he1);
    cudaGetSymbolAddress((void**)&score, g_score);
    cudaGetSymbolAddress((void**)&bsum, g_bsum);
    cudaGetSymbolAddress((void**)&cnt, g_cnt);
    cudaGetSymbolAddress((void**)&off, g_off);
    cudaGetSymbolAddress((void**)&cur, g_cur);
    cudaGetSymbolAddress((void**)&csrc, g_csrc);
    cudaGetSymbolAddress((void**)&wth, g_wth);
    cudaGetSymbolAddress((void**)&wtl, g_wtl);
    cudaGetSymbolAddress((void**)&bigh, g_bigh);
    cudaGetSymbolAddress((void**)&bigl, g_bigl);
    cudaGetSymbolAddress((void**)&pth, g_pth);
    cudaGetSymbolAddress((void**)&ptl, g_ptl);
    cudaGetSymbolAddress((void**)&phwh[0], g_phw0h);
    cudaGetSymbolAddress((void**)&phwl[0], g_phw0l);
    cudaGetSymbolAddress((void**)&phwh[1], g_phw1h);
    cudaGetSymbolAddress((void**)&phwl[1], g_phw1l);
    cudaGetSymbolAddress((void**)&pheh[0], g_phe0h);
    cudaGetSymbolAddress((void**)&phel[0], g_phe0l);
    cudaGetSymbolAddress((void**)&pheh[1], g_phe1h);
    cudaGetSymbolAddress((void**)&phel[1], g_phe1l);
    cudaGetSymbolAddress((void**)&pa0h, g_pa0h);
    cudaGetSymbolAddress((void**)&pa0l, g_pa0l);
    cudaGetSymbolAddress((void**)&pa1h, g_pa1h);
    cudaGetSymbolAddress((void**)&pa1l, g_pa1l);
    cudaGetSymbolAddress((void**)&pa2h, g_pa2h);
    cudaGetSymbolAddress((void**)&pa2l, g_pa2l);

    const int* es[3] = { e_near, e_refer + 0, e_close };          // src rows
    const int* ed[3] = { e_near + EDG, e_refer + EDG, e_close + EDG };
    // relation order: 0=near(dst win), 1=refer(dst win), 2=close(dst ex)
    es[1] = e_refer;

    const unsigned edge_blocks = (EDG + 255) / 256;

    // --- weight conversion ---
    {
        dim3 blk(32, 8);
        dim3 gHH(HDIM / 32, HDIM / 32);
        for (int l = 0; l < NLAYERS; l++) {
            size_t s = (size_t)l * HDIM * HDIM;
            conv_w<<<gHH, blk>>>(Wl_near + s, nullptr, HDIM, HDIM, HDIM, wth + WOFF_WLN(l), wtl + WOFF_WLN(l));
            conv_w<<<gHH, blk>>>(Wl_refer + s, nullptr, HDIM, HDIM, HDIM, wth + WOFF_WLR(l), wtl + WOFF_WLR(l));
            conv_w<<<gHH, blk>>>(Wr_near + s, Wr_refer + s, HDIM, HDIM, HDIM, wth + WOFF_WSUM(l), wtl + WOFF_WSUM(l));
            conv_w<<<gHH, blk>>>(Wl_close + s, nullptr, HDIM, HDIM, HDIM, wth + WOFF_WLC(l), wtl + WOFF_WLC(l));
            conv_w<<<gHH, blk>>>(Wr_close + s, nullptr, HDIM, HDIM, HDIM, wth + WOFF_WRC(l), wtl + WOFF_WRC(l));
            bias_sum<<<(HDIM + 255) / 256, 256>>>(b_near + (size_t)l * HDIM, b_refer + (size_t)l * HDIM,
                                                  bsum + (size_t)l * HDIM, HDIM);
        }
        conv_w<<<gHH, blk>>>(W_post, nullptr, HDIM, HDIM, HDIM, wth + WOFF_POST, wtl + WOFF_POST);
        dim3 gWIN(KP_WIN / 32, HDIM / 32);
        conv_w<<<gWIN, blk>>>(W_win, nullptr, KWIN, HDIM, KP_WIN, wth + WOFF_WIN, wtl + WOFF_WIN);
        dim3 gEXP(128 / 32, HDIM / 32);
        conv_w<<<gEXP, blk>>>(W_exp, nullptr, KEXP, HDIM, 128, wth + WOFF_EXP, wtl + WOFF_EXP);
        dim3 gLIN(HDIM / 32, 128 / 32);
        conv_w<<<gLIN, blk>>>(W_lin, nullptr, HDIM, NOUT, HDIM, wth + WOFF_LIN, wtl + WOFF_LIN);
    }

    // --- zero pad rows of GEMM-written plane buffers (once per launch) ---
    {
        const int padtot = (MP - NWIN) * HDIM;
        const unsigned pb = (padtot + 255) / 256;
        zero_pad<<<pb, 256>>>(pth, ptl);
        zero_pad<<<pb, 256>>>(phwh[0], phwl[0]);
        zero_pad<<<pb, 256>>>(phwh[1], phwl[1]);
        zero_pad<<<pb, 256>>>(pheh[0], phel[0]);
        zero_pad<<<pb, 256>>>(pheh[1], phel[1]);
    }

    // --- CSR build (3 relations) ---
    zero_int<<<(3 * NWIN + 255) / 256, 256>>>(cnt, 3 * NWIN);
    for (int r = 0; r < 3; r++) {
        hist_kernel<<<edge_blocks, 256>>>(ed[r], cnt + r * NWIN, EDG);
        scan_kernel<<<1, 1024>>>(cnt + r * NWIN, off + r * (NWIN + 1), cur + r * NWIN, NWIN);
        csr_fill<<<edge_blocks, 256>>>(es[r], ed[r], cur + r * NWIN, csrc + (size_t)r * EDG, EDG);
    }

    // --- input projections: h = lrelu(lrelu(x@W)@W_post) ---
    {
        long long tot = (long long)MP * 128;
        conv_a<<<(unsigned)((tot + 255) / 256), 256>>>(x_example, NEX, KEXP, 128, tot, pa0h, pa0l);
        OpDesc op = { pa0h, pa0l, wth + WOFF_EXP, wtl + WOFF_EXP, 128 };
        launch_gemm(&op, 1, NEX, HDIM, HDIM, HDIM, nullptr, 1.f, 1, nullptr, pth, ptl);
        op = { pth, ptl, wth + WOFF_POST, wtl + WOFF_POST, HDIM };
        launch_gemm(&op, 1, NEX, HDIM, HDIM, HDIM, nullptr, 1.f, 1, he[0], pheh[0], phel[0]);

        tot = (long long)MP * KP_WIN;
        conv_a<<<(unsigned)((tot + 255) / 256), 256>>>(x_window, NWIN, KWIN, KP_WIN, tot, bigh, bigl);
        op = { bigh, bigl, wth + WOFF_WIN, wtl + WOFF_WIN, KP_WIN };
        launch_gemm(&op, 1, NWIN, HDIM, HDIM, HDIM, nullptr, 1.f, 1, nullptr, pth, ptl);
        op = { pth, ptl, wth + WOFF_POST, wtl + WOFF_POST, HDIM };
        launch_gemm(&op, 1, NWIN, HDIM, HDIM, HDIM, nullptr, 1.f, 1, hw[0], phwh[0], phwl[0]);
    }

    // --- SAGE layers ---
    int curb = 0;
    for (int l = 0; l < NLAYERS; l++) {
        int nxt = curb ^ 1;
        // gather means -> bf16 planes (mean fold inside)
        gather_mean<<<MP, 128>>>(hw[curb], off + 0 * (NWIN + 1), csrc + 0 * (size_t)EDG, NWIN, pa0h, pa0l);
        gather_mean<<<MP, 128>>>(he[curb], off + 1 * (NWIN + 1), csrc + 1 * (size_t)EDG, NWIN, pa1h, pa1l);
        gather_mean<<<MP, 128>>>(he[curb], off + 2 * (NWIN + 1), csrc + 2 * (size_t)EDG, NEX, pa2h, pa2l);

        // window: lrelu(0.5*(a0@WlN + a1@WlR + hw@(WrN+WrR) + bN+bR))
        OpDesc ops3[3] = {
            { pa0h, pa0l, wth + WOFF_WLN(l), wtl + WOFF_WLN(l), HDIM },
            { pa1h, pa1l, wth + WOFF_WLR(l), wtl + WOFF_WLR(l), HDIM },
            { phwh[curb], phwl[curb], wth + WOFF_WSUM(l), wtl + WOFF_WSUM(l), HDIM },
        };
        launch_gemm(ops3, 3, NWIN, HDIM, HDIM, HDIM, bsum + (size_t)l * HDIM, 0.5f, 1,
                    hw[nxt], phwh[nxt], phwl[nxt]);

        // example: lrelu(a2@WlC + he@WrC + bC)
        OpDesc ops2[2] = {
            { pa2h, pa2l, wth + WOFF_WLC(l), wtl + WOFF_WLC(l), HDIM },
            { pheh[curb], phel[curb], wth + WOFF_WRC(l), wtl + WOFF_WRC(l), HDIM },
        };
        launch_gemm(ops2, 2, NEX, HDIM, HDIM, HDIM, b_close + (size_t)l * HDIM, 1.f, 1,
                    he[nxt], pheh[nxt], phel[nxt]);
        curb = nxt;
    }

    // --- CSRA pooling (refer CSR, relation 1) -> planes of (hw + 0.5*pooled) ---
    gemv_score<<<(NEX + 7) / 8, 256>>>(he[curb], w_pool, score);
    pool_gather<<<MP, 128>>>(he[curb], hw[curb], score,
                             off + 1 * (NWIN + 1), csrc + 1 * (size_t)EDG, NWIN, pth, ptl);

    // out = planes @ W_lin + b_lin
    OpDesc opf = { pth, ptl, wth + WOFF_LIN, wtl + WOFF_LIN, HDIM };
    launch_gemm(&opf, 1, NWIN, 128, NOUT, NOUT, b_lin, 1.f, 0, out, nullptr, nullptr);
}